// round 9
// baseline (speedup 1.0000x reference)
#include <cuda_runtime.h>
#include <cstdint>

// Problem constants (match reference_code)
#define N0c 200000
#define N1c 50000
#define N2c 12500
#define N3c 3200
#define E0c 500000
#define E1c 125000
#define E2c 32000
#define DINc 128
#define DHc 256
#define DOUTc 128

// ---------------- scratch (static device globals; no allocations) ----------------
__device__ float g_mean[(size_t)N1c * DHc];
__device__ float g_h1[(size_t)N1c * DHc];
__device__ float g_h2[(size_t)N2c * DHc];
__device__ int g_deg0[N1c]; __device__ int g_off0[N1c + 1]; __device__ int g_cur0[N1c]; __device__ int g_esrc0[E0c];
__device__ int g_deg1[N2c]; __device__ int g_off1[N2c + 1]; __device__ int g_cur1[N2c]; __device__ int g_esrc1[E1c];
__device__ int g_deg2[N3c]; __device__ int g_off2[N3c + 1]; __device__ int g_cur2[N3c]; __device__ int g_esrc2[E2c];

// ---------------- batched CSR build (all 3 layers in one pass each) ----------------
__global__ void zero3_kernel() {
    int i = blockIdx.x * blockDim.x + threadIdx.x;
    if (i < N1c) g_deg0[i] = 0;
    else if (i < N1c + N2c) g_deg1[i - N1c] = 0;
    else if (i < N1c + N2c + N3c) g_deg2[i - N1c - N2c] = 0;
}

__global__ void hist3_kernel(const int* __restrict__ d0, const int* __restrict__ d1,
                             const int* __restrict__ d2) {
    int e = blockIdx.x * blockDim.x + threadIdx.x;
    if (e < E0c) atomicAdd(&g_deg0[d0[e]], 1);
    else if (e < E0c + E1c) atomicAdd(&g_deg1[d1[e - E0c]], 1);
    else if (e < E0c + E1c + E2c) atomicAdd(&g_deg2[d2[e - E0c - E1c]], 1);
}

// One block per layer; chunked one-pass scan (1024 threads).
__global__ void scan3_kernel() {
    const int T = 1024;
    __shared__ int wsum[32];
    int layer = blockIdx.x;
    int n = (layer == 0) ? N1c : (layer == 1) ? N2c : N3c;
    int E = (layer == 0) ? E0c : (layer == 1) ? E1c : E2c;
    int* deg = (layer == 0) ? g_deg0 : (layer == 1) ? g_deg1 : g_deg2;
    int* off = (layer == 0) ? g_off0 : (layer == 1) ? g_off1 : g_off2;
    int* cur = (layer == 0) ? g_cur0 : (layer == 1) ? g_cur1 : g_cur2;

    int tid = threadIdx.x, lane = tid & 31, wid = tid >> 5;
    int chunk = (n + T - 1) / T;
    int beg = min(tid * chunk, n), end = min(beg + chunk, n);

    int sum = 0;
    for (int i = beg; i < end; i++) sum += deg[i];

    int s = sum;
    #pragma unroll
    for (int o = 1; o < 32; o <<= 1) {
        int t = __shfl_up_sync(0xffffffffu, s, o);
        if (lane >= o) s += t;
    }
    if (lane == 31) wsum[wid] = s;
    __syncthreads();
    if (wid == 0) {
        int ws = wsum[lane];
        #pragma unroll
        for (int o = 1; o < 32; o <<= 1) {
            int t = __shfl_up_sync(0xffffffffu, ws, o);
            if (lane >= o) ws += t;
        }
        wsum[lane] = ws;
    }
    __syncthreads();
    int excl = s - sum + ((wid > 0) ? wsum[wid - 1] : 0);

    int run = excl;
    for (int i = beg; i < end; i++) {
        int d = deg[i];
        off[i] = run;
        cur[i] = run;
        run += d;
    }
    if (tid == 0) off[n] = E;
}

__global__ void bucket3_kernel(const int* __restrict__ s0, const int* __restrict__ d0,
                               const int* __restrict__ s1, const int* __restrict__ d1,
                               const int* __restrict__ s2, const int* __restrict__ d2) {
    int e = blockIdx.x * blockDim.x + threadIdx.x;
    if (e < E0c) {
        int p = atomicAdd(&g_cur0[d0[e]], 1);
        g_esrc0[p] = s0[e];
    } else if (e < E0c + E1c) {
        int i = e - E0c;
        int p = atomicAdd(&g_cur1[d1[i]], 1);
        g_esrc1[p] = s1[i];
    } else if (e < E0c + E1c + E2c) {
        int i = e - E0c - E1c;
        int p = atomicAdd(&g_cur2[d2[i]], 1);
        g_esrc2[p] = s2[i];
    }
}

// ---------------- aggregation: warp per target node, register accumulation ----------------
template <int D>
__global__ void aggregate_kernel(const float* __restrict__ X, float* __restrict__ mean,
                                 const int* __restrict__ off, const int* __restrict__ esrc,
                                 int n_tgt) {
    int w = (blockIdx.x * blockDim.x + threadIdx.x) >> 5;
    int lane = threadIdx.x & 31;
    if (w >= n_tgt) return;
    int beg = off[w], end = off[w + 1];
    float acc[D / 32];
    #pragma unroll
    for (int i = 0; i < D / 32; i++) acc[i] = 0.f;
    int e = beg;
    for (; e + 1 < end; e += 2) {
        int s0 = esrc[e], s1 = esrc[e + 1];
        const float4* r0 = (const float4*)(X + (size_t)s0 * D);
        const float4* r1 = (const float4*)(X + (size_t)s1 * D);
        #pragma unroll
        for (int i = 0; i < D / 128; i++) {
            float4 v0 = r0[lane + 32 * i];
            float4 v1 = r1[lane + 32 * i];
            acc[4 * i + 0] += v0.x + v1.x;
            acc[4 * i + 1] += v0.y + v1.y;
            acc[4 * i + 2] += v0.z + v1.z;
            acc[4 * i + 3] += v0.w + v1.w;
        }
    }
    if (e < end) {
        const float4* row = (const float4*)(X + (size_t)esrc[e] * D);
        #pragma unroll
        for (int i = 0; i < D / 128; i++) {
            float4 v = row[lane + 32 * i];
            acc[4 * i + 0] += v.x;
            acc[4 * i + 1] += v.y;
            acc[4 * i + 2] += v.z;
            acc[4 * i + 3] += v.w;
        }
    }
    float inv = 1.f / (float)max(end - beg, 1);
    float4* mrow = (float4*)(mean + (size_t)w * D);
    #pragma unroll
    for (int i = 0; i < D / 128; i++) {
        float4 o;
        o.x = acc[4 * i + 0] * inv;
        o.y = acc[4 * i + 1] * inv;
        o.z = acc[4 * i + 2] * inv;
        o.w = acc[4 * i + 3] * inv;
        mrow[lane + 32 * i] = o;
    }
}

// ---------------- tf32 tensor-core fused dual-A GEMM, fragment-major smem ----------------
// out = act( mean@Wl^T + Xtgt@Wr^T + b )
// Block tile 128x128, BK=32, 256 threads = 8 warps (2m x 4n), warp tile 64x32
// (4x4 m16n8k8 tf32 mma), cvt once at STS time (R2 numerics).
// NEW: smem stored fragment-major so the inner loop does 4x LDS.128 (A) +
// 4x LDS.64 (B) per k8-step instead of 24 scalar LDS.32.
//
// As2[(mi8*4 + ks8)*32 + lane][w]: w = {(g,t),(g+8,t),(g,t+4),(g+8,t+4)}
//   of A-block (mi8*16 rows, ks8*8 k), lane = g*4+t.
// Bs2[(ni8*4 + ks8)*32 + lane][w]: w = {(g,t),(g,t+4)} of B-block (ni8*8 n rows).

__device__ __forceinline__ uint32_t f2tf32(float f) {
    uint32_t u;
    asm("cvt.rna.tf32.f32 %0, %1;" : "=r"(u) : "f"(f));
    return u;
}

__global__ void __launch_bounds__(256) sage_gemm_tf32(
    const float* __restrict__ A0, const float* __restrict__ A1,
    const float* __restrict__ Wl, const float* __restrict__ Wr,
    const float* __restrict__ bias, float* __restrict__ out,
    int M, int N, int D, int relu)
{
    __shared__ uint32_t As2[8 * 4 * 32 * 4];   // 16 KB
    __shared__ uint32_t Bs2[16 * 4 * 32 * 2];  // 16 KB

    int tid = threadIdx.x;
    int lane = tid & 31, wid = tid >> 5;
    int wm = wid & 1;        // 0..1  -> 64-row half
    int wn = wid >> 1;       // 0..3  -> 32-col strip
    int rowBase = blockIdx.x * 128, colBase = blockIdx.y * 128;

    float acc[4][4][4];
    #pragma unroll
    for (int i = 0; i < 4; i++)
        #pragma unroll
        for (int j = 0; j < 4; j++)
            #pragma unroll
            for (int r = 0; r < 4; r++) acc[i][j][r] = 0.f;

    int ldr = tid >> 3;          // 0..31 (row within 32-row chunk)
    int ldc = (tid & 7) * 4;     // 0,4,...,28 (k offset)
    int ksW = ldc >> 3;          // k8 block of this thread's stage slice
    int khW = (ldc >> 2) & 1;    // k-half within the k8 block

    for (int kt = 0; kt < 2 * D; kt += 32) {
        const float* A = (kt < D) ? A0 : A1;
        const float* W = (kt < D) ? Wl : Wr;
        int kk = (kt < D) ? kt : (kt - D);

        #pragma unroll
        for (int s = 0; s < 4; s++) {
            int r = ldr + s * 32;
            // ---- A element (r, ldc+j) ----
            int grow = rowBase + r;
            float4 v = make_float4(0.f, 0.f, 0.f, 0.f);
            if (grow < M) v = *(const float4*)(A + (size_t)grow * D + kk + ldc);
            {
                int mi8 = r >> 4;
                int gA = r & 7;
                int rh = (r >> 3) & 1;
                uint32_t* slot = &As2[(((mi8 * 4 + ksW) * 32 + gA * 4) << 2) + rh + 2 * khW];
                slot[0]  = f2tf32(v.x);
                slot[4]  = f2tf32(v.y);
                slot[8]  = f2tf32(v.z);
                slot[12] = f2tf32(v.w);
            }
            // ---- B element (n=r, ldc+j) ----
            float4 w = *(const float4*)(W + (size_t)(colBase + r) * D + kk + ldc);
            {
                int ni8 = r >> 3;
                int gB = r & 7;
                uint32_t* slot = &Bs2[(((ni8 * 4 + ksW) * 32 + gB * 4) << 1) + khW];
                slot[0] = f2tf32(w.x);
                slot[2] = f2tf32(w.y);
                slot[4] = f2tf32(w.z);
                slot[6] = f2tf32(w.w);
            }
        }
        __syncthreads();

        #pragma unroll
        for (int ks8 = 0; ks8 < 4; ks8++) {
            uint4 af[4];
            #pragma unroll
            for (int mi = 0; mi < 4; mi++)
                af[mi] = *(const uint4*)&As2[(((wm * 4 + mi) * 4 + ks8) * 32 + lane) << 2];
            uint2 bf[4];
            #pragma unroll
            for (int ni = 0; ni < 4; ni++)
                bf[ni] = *(const uint2*)&Bs2[(((wn * 4 + ni) * 4 + ks8) * 32 + lane) << 1];
            #pragma unroll
            for (int mi = 0; mi < 4; mi++)
                #pragma unroll
                for (int ni = 0; ni < 4; ni++) {
                    asm volatile(
                        "mma.sync.aligned.m16n8k8.row.col.f32.tf32.tf32.f32 "
                        "{%0,%1,%2,%3}, {%4,%5,%6,%7}, {%8,%9}, {%0,%1,%2,%3};"
                        : "+f"(acc[mi][ni][0]), "+f"(acc[mi][ni][1]),
                          "+f"(acc[mi][ni][2]), "+f"(acc[mi][ni][3])
                        : "r"(af[mi].x), "r"(af[mi].y), "r"(af[mi].z), "r"(af[mi].w),
                          "r"(bf[ni].x), "r"(bf[ni].y));
                }
        }
        __syncthreads();
    }

    // epilogue: bias + optional relu
    int g = lane >> 2, t = lane & 3;
    #pragma unroll
    for (int mi = 0; mi < 4; mi++) {
        #pragma unroll
        for (int ni = 0; ni < 4; ni++) {
            int col = colBase + wn * 32 + ni * 8 + t * 2;
            float b0v = bias[col], b1v = bias[col + 1];
            int row0 = rowBase + wm * 64 + mi * 16 + g;
            if (row0 < M) {
                float2 o;
                o.x = acc[mi][ni][0] + b0v;
                o.y = acc[mi][ni][1] + b1v;
                if (relu) { o.x = fmaxf(o.x, 0.f); o.y = fmaxf(o.y, 0.f); }
                *(float2*)(out + (size_t)row0 * N + col) = o;
            }
            int row1 = row0 + 8;
            if (row1 < M) {
                float2 o;
                o.x = acc[mi][ni][2] + b0v;
                o.y = acc[mi][ni][3] + b1v;
                if (relu) { o.x = fmaxf(o.x, 0.f); o.y = fmaxf(o.y, 0.f); }
                *(float2*)(out + (size_t)row1 * N + col) = o;
            }
        }
    }
}

// ---------------- host-side layer driver (compute only; CSR done up front) ----------------
static void run_layer(const float* X, const int* off, const int* esrc,
                      int n_tgt, int D,
                      const float* Wl, const float* Wr, const float* b,
                      float* outbuf, int Nout, int relu)
{
    float* mean;
    cudaGetSymbolAddress((void**)&mean, g_mean);

    int aggBlocks = (n_tgt * 32 + 255) / 256;
    if (D == 128)
        aggregate_kernel<128><<<aggBlocks, 256>>>(X, mean, off, esrc, n_tgt);
    else
        aggregate_kernel<256><<<aggBlocks, 256>>>(X, mean, off, esrc, n_tgt);

    dim3 grid((n_tgt + 127) / 128, Nout / 128);
    sage_gemm_tf32<<<grid, 256>>>(mean, X, Wl, Wr, b, outbuf, n_tgt, Nout, D, relu);
}

extern "C" void kernel_launch(void* const* d_in, const int* in_sizes, int n_in,
                              void* d_out, int out_size)
{
    const float* x    = (const float*)d_in[0];
    const int*   src0 = (const int*)d_in[1];
    const int*   dst0 = (const int*)d_in[2];
    const int*   src1 = (const int*)d_in[3];
    const int*   dst1 = (const int*)d_in[4];
    const int*   src2 = (const int*)d_in[5];
    const int*   dst2 = (const int*)d_in[6];
    const float* wl0  = (const float*)d_in[7];
    const float* wr0  = (const float*)d_in[8];
    const float* b0   = (const float*)d_in[9];
    const float* wl1  = (const float*)d_in[10];
    const float* wr1  = (const float*)d_in[11];
    const float* b1   = (const float*)d_in[12];
    const float* wl2  = (const float*)d_in[13];
    const float* wr2  = (const float*)d_in[14];
    const float* b2   = (const float*)d_in[15];
    float* out = (float*)d_out;

    float *h1, *h2;
    cudaGetSymbolAddress((void**)&h1, g_h1);
    cudaGetSymbolAddress((void**)&h2, g_h2);
    int *off0, *off1, *off2, *es0, *es1, *es2;
    cudaGetSymbolAddress((void**)&off0, g_off0);
    cudaGetSymbolAddress((void**)&off1, g_off1);
    cudaGetSymbolAddress((void**)&off2, g_off2);
    cudaGetSymbolAddress((void**)&es0, g_esrc0);
    cudaGetSymbolAddress((void**)&es1, g_esrc1);
    cudaGetSymbolAddress((void**)&es2, g_esrc2);

    // Batched CSR build for all 3 layers (feature-independent)
    const int NTOT = N1c + N2c + N3c;
    const int ETOT = E0c + E1c + E2c;
    zero3_kernel<<<(NTOT + 255) / 256, 256>>>();
    hist3_kernel<<<(ETOT + 255) / 256, 256>>>(dst0, dst1, dst2);
    scan3_kernel<<<3, 1024>>>();
    bucket3_kernel<<<(ETOT + 255) / 256, 256>>>(src0, dst0, src1, dst1, src2, dst2);

    // Layer 0: x (N0 x 128) -> h1 (N1 x 256), relu
    run_layer(x,  off0, es0, N1c, DINc, wl0, wr0, b0, h1, DHc, 1);
    // Layer 1: h1 (N1 x 256) -> h2 (N2 x 256), relu
    run_layer(h1, off1, es1, N2c, DHc, wl1, wr1, b1, h2, DHc, 1);
    // Layer 2: h2 (N2 x 256) -> out (N3 x 128), no relu
    run_layer(h2, off2, es2, N3c, DHc, wl2, wr2, b2, out, DOUTc, 0);
}

// round 10
// speedup vs baseline: 1.0923x; 1.0923x over previous
#include <cuda_runtime.h>
#include <cstdint>

// Problem constants (match reference_code)
#define N0c 200000
#define N1c 50000
#define N2c 12500
#define N3c 3200
#define E0c 500000
#define E1c 125000
#define E2c 32000
#define DINc 128
#define DHc 256
#define DOUTc 128

// ---------------- scratch (static device globals; no allocations) ----------------
__device__ float g_mean[(size_t)N1c * DHc];
__device__ float g_h1[(size_t)N1c * DHc];
__device__ float g_h2[(size_t)N2c * DHc];
__device__ int g_deg0[N1c]; __device__ int g_off0[N1c + 1]; __device__ int g_cur0[N1c]; __device__ int g_esrc0[E0c];
__device__ int g_deg1[N2c]; __device__ int g_off1[N2c + 1]; __device__ int g_cur1[N2c]; __device__ int g_esrc1[E1c];
__device__ int g_deg2[N3c]; __device__ int g_off2[N3c + 1]; __device__ int g_cur2[N3c]; __device__ int g_esrc2[E2c];

// ---------------- batched CSR build ----------------
__global__ void zero3_kernel() {
    int i = blockIdx.x * blockDim.x + threadIdx.x;
    if (i < N1c) g_deg0[i] = 0;
    else if (i < N1c + N2c) g_deg1[i - N1c] = 0;
    else if (i < N1c + N2c + N3c) g_deg2[i - N1c - N2c] = 0;
}

__global__ void hist3_kernel(const int* __restrict__ d0, const int* __restrict__ d1,
                             const int* __restrict__ d2) {
    int e = blockIdx.x * blockDim.x + threadIdx.x;
    if (e < E0c) atomicAdd(&g_deg0[d0[e]], 1);
    else if (e < E0c + E1c) atomicAdd(&g_deg1[d1[e - E0c]], 1);
    else if (e < E0c + E1c + E2c) atomicAdd(&g_deg2[d2[e - E0c - E1c]], 1);
}

__global__ void scan3_kernel() {
    const int T = 1024;
    __shared__ int wsum[32];
    int layer = blockIdx.x;
    int n = (layer == 0) ? N1c : (layer == 1) ? N2c : N3c;
    int E = (layer == 0) ? E0c : (layer == 1) ? E1c : E2c;
    int* deg = (layer == 0) ? g_deg0 : (layer == 1) ? g_deg1 : g_deg2;
    int* off = (layer == 0) ? g_off0 : (layer == 1) ? g_off1 : g_off2;
    int* cur = (layer == 0) ? g_cur0 : (layer == 1) ? g_cur1 : g_cur2;

    int tid = threadIdx.x, lane = tid & 31, wid = tid >> 5;
    int chunk = (n + T - 1) / T;
    int beg = min(tid * chunk, n), end = min(beg + chunk, n);

    int sum = 0;
    for (int i = beg; i < end; i++) sum += deg[i];

    int s = sum;
    #pragma unroll
    for (int o = 1; o < 32; o <<= 1) {
        int t = __shfl_up_sync(0xffffffffu, s, o);
        if (lane >= o) s += t;
    }
    if (lane == 31) wsum[wid] = s;
    __syncthreads();
    if (wid == 0) {
        int ws = wsum[lane];
        #pragma unroll
        for (int o = 1; o < 32; o <<= 1) {
            int t = __shfl_up_sync(0xffffffffu, ws, o);
            if (lane >= o) ws += t;
        }
        wsum[lane] = ws;
    }
    __syncthreads();
    int excl = s - sum + ((wid > 0) ? wsum[wid - 1] : 0);

    int run = excl;
    for (int i = beg; i < end; i++) {
        int d = deg[i];
        off[i] = run;
        cur[i] = run;
        run += d;
    }
    if (tid == 0) off[n] = E;
}

__global__ void bucket3_kernel(const int* __restrict__ s0, const int* __restrict__ d0,
                               const int* __restrict__ s1, const int* __restrict__ d1,
                               const int* __restrict__ s2, const int* __restrict__ d2) {
    int e = blockIdx.x * blockDim.x + threadIdx.x;
    if (e < E0c) {
        int p = atomicAdd(&g_cur0[d0[e]], 1);
        g_esrc0[p] = s0[e];
    } else if (e < E0c + E1c) {
        int i = e - E0c;
        int p = atomicAdd(&g_cur1[d1[i]], 1);
        g_esrc1[p] = s1[i];
    } else if (e < E0c + E1c + E2c) {
        int i = e - E0c - E1c;
        int p = atomicAdd(&g_cur2[d2[i]], 1);
        g_esrc2[p] = s2[i];
    }
}

// ---------------- aggregation: warp per target node ----------------
template <int D>
__global__ void aggregate_kernel(const float* __restrict__ X, float* __restrict__ mean,
                                 const int* __restrict__ off, const int* __restrict__ esrc,
                                 int n_tgt) {
    int w = (blockIdx.x * blockDim.x + threadIdx.x) >> 5;
    int lane = threadIdx.x & 31;
    if (w >= n_tgt) return;
    int beg = off[w], end = off[w + 1];
    float acc[D / 32];
    #pragma unroll
    for (int i = 0; i < D / 32; i++) acc[i] = 0.f;
    int e = beg;
    for (; e + 1 < end; e += 2) {
        int s0 = esrc[e], s1 = esrc[e + 1];
        const float4* r0 = (const float4*)(X + (size_t)s0 * D);
        const float4* r1 = (const float4*)(X + (size_t)s1 * D);
        #pragma unroll
        for (int i = 0; i < D / 128; i++) {
            float4 v0 = r0[lane + 32 * i];
            float4 v1 = r1[lane + 32 * i];
            acc[4 * i + 0] += v0.x + v1.x;
            acc[4 * i + 1] += v0.y + v1.y;
            acc[4 * i + 2] += v0.z + v1.z;
            acc[4 * i + 3] += v0.w + v1.w;
        }
    }
    if (e < end) {
        const float4* row = (const float4*)(X + (size_t)esrc[e] * D);
        #pragma unroll
        for (int i = 0; i < D / 128; i++) {
            float4 v = row[lane + 32 * i];
            acc[4 * i + 0] += v.x;
            acc[4 * i + 1] += v.y;
            acc[4 * i + 2] += v.z;
            acc[4 * i + 3] += v.w;
        }
    }
    float inv = 1.f / (float)max(end - beg, 1);
    float4* mrow = (float4*)(mean + (size_t)w * D);
    #pragma unroll
    for (int i = 0; i < D / 128; i++) {
        float4 o;
        o.x = acc[4 * i + 0] * inv;
        o.y = acc[4 * i + 1] * inv;
        o.z = acc[4 * i + 2] * inv;
        o.w = acc[4 * i + 3] * inv;
        mrow[lane + 32 * i] = o;
    }
}

__device__ __forceinline__ uint32_t f2tf32(float f) {
    uint32_t u;
    asm("cvt.rna.tf32.f32 %0, %1;" : "=r"(u) : "f"(f));
    return u;
}

// ---------------- tf32 GEMM, BN=256 single-block variant (N==256 layers) ----------------
// 512 threads = 16 warps (2m x 8n), warp tile 64x32, BK=32, R2 inner loop.
// A staged once per 128-row strip (no grid.y), B covers all 256 cols.
#define LDS_ 36
#define WIDE_SMEM ((128 + 256) * LDS_ * 4)   // 55296 B

__global__ void __launch_bounds__(512) sage_gemm_wide(
    const float* __restrict__ A0, const float* __restrict__ A1,
    const float* __restrict__ Wl, const float* __restrict__ Wr,
    const float* __restrict__ bias, float* __restrict__ out,
    int M, int D, int relu)
{
    const int N = 256;
    extern __shared__ uint32_t smw[];
    uint32_t* As = smw;                 // 128 * 36
    uint32_t* Bs = smw + 128 * LDS_;    // 256 * 36

    int tid = threadIdx.x;
    int lane = tid & 31, wid = tid >> 5;
    int wm = wid & 1;        // 64-row half
    int wn = wid >> 1;       // 0..7, 32-col strip
    int g = lane >> 2, t = lane & 3;

    int rowBase = blockIdx.x * 128;

    float acc[4][4][4];
    #pragma unroll
    for (int i = 0; i < 4; i++)
        #pragma unroll
        for (int j = 0; j < 4; j++)
            #pragma unroll
            for (int r = 0; r < 4; r++) acc[i][j][r] = 0.f;

    for (int kt = 0; kt < 2 * D; kt += 32) {
        const float* A = (kt < D) ? A0 : A1;
        const float* W = (kt < D) ? Wl : Wr;
        int kk = (kt < D) ? kt : (kt - D);

        // A tile: 128 rows x 32 k = 1024 float4 slots over 512 threads (2 iters)
        #pragma unroll
        for (int s = 0; s < 2; s++) {
            int idx = tid + 512 * s;
            int r = idx >> 3, kg = (idx & 7) * 4;
            int grow = rowBase + r;
            float4 v = make_float4(0.f, 0.f, 0.f, 0.f);
            if (grow < M) v = *(const float4*)(A + (size_t)grow * D + kk + kg);
            uint4 ua;
            ua.x = f2tf32(v.x); ua.y = f2tf32(v.y); ua.z = f2tf32(v.z); ua.w = f2tf32(v.w);
            *(uint4*)&As[r * LDS_ + kg] = ua;
        }
        // B tile: 256 rows x 32 k = 2048 slots (4 iters)
        #pragma unroll
        for (int s = 0; s < 4; s++) {
            int idx = tid + 512 * s;
            int r = idx >> 3, kg = (idx & 7) * 4;
            float4 w = *(const float4*)(W + (size_t)r * D + kk + kg);
            uint4 ub;
            ub.x = f2tf32(w.x); ub.y = f2tf32(w.y); ub.z = f2tf32(w.z); ub.w = f2tf32(w.w);
            *(uint4*)&Bs[r * LDS_ + kg] = ub;
        }
        __syncthreads();

        #pragma unroll
        for (int ks = 0; ks < 32; ks += 8) {
            uint32_t af[4][4];
            #pragma unroll
            for (int mi = 0; mi < 4; mi++) {
                int m = wm * 64 + mi * 16;
                af[mi][0] = As[(m + g)     * LDS_ + ks + t];
                af[mi][1] = As[(m + g + 8) * LDS_ + ks + t];
                af[mi][2] = As[(m + g)     * LDS_ + ks + t + 4];
                af[mi][3] = As[(m + g + 8) * LDS_ + ks + t + 4];
            }
            uint32_t bf[4][2];
            #pragma unroll
            for (int ni = 0; ni < 4; ni++) {
                int n = wn * 32 + ni * 8;
                bf[ni][0] = Bs[(n + g) * LDS_ + ks + t];
                bf[ni][1] = Bs[(n + g) * LDS_ + ks + t + 4];
            }
            #pragma unroll
            for (int mi = 0; mi < 4; mi++)
                #pragma unroll
                for (int ni = 0; ni < 4; ni++) {
                    asm volatile(
                        "mma.sync.aligned.m16n8k8.row.col.f32.tf32.tf32.f32 "
                        "{%0,%1,%2,%3}, {%4,%5,%6,%7}, {%8,%9}, {%0,%1,%2,%3};"
                        : "+f"(acc[mi][ni][0]), "+f"(acc[mi][ni][1]),
                          "+f"(acc[mi][ni][2]), "+f"(acc[mi][ni][3])
                        : "r"(af[mi][0]), "r"(af[mi][1]), "r"(af[mi][2]), "r"(af[mi][3]),
                          "r"(bf[ni][0]), "r"(bf[ni][1]));
                }
        }
        __syncthreads();
    }

    #pragma unroll
    for (int mi = 0; mi < 4; mi++) {
        #pragma unroll
        for (int ni = 0; ni < 4; ni++) {
            int col = wn * 32 + ni * 8 + t * 2;
            float b0v = bias[col], b1v = bias[col + 1];
            int row0 = rowBase + wm * 64 + mi * 16 + g;
            if (row0 < M) {
                float2 o;
                o.x = acc[mi][ni][0] + b0v;
                o.y = acc[mi][ni][1] + b1v;
                if (relu) { o.x = fmaxf(o.x, 0.f); o.y = fmaxf(o.y, 0.f); }
                *(float2*)(out + (size_t)row0 * N + col) = o;
            }
            int row1 = row0 + 8;
            if (row1 < M) {
                float2 o;
                o.x = acc[mi][ni][2] + b0v;
                o.y = acc[mi][ni][3] + b1v;
                if (relu) { o.x = fmaxf(o.x, 0.f); o.y = fmaxf(o.y, 0.f); }
                *(float2*)(out + (size_t)row1 * N + col) = o;
            }
        }
    }
}

// ---------------- R2 GEMM (256 threads, BN=128) for the N=128 layer ----------------
__global__ void __launch_bounds__(256) sage_gemm_tf32(
    const float* __restrict__ A0, const float* __restrict__ A1,
    const float* __restrict__ Wl, const float* __restrict__ Wr,
    const float* __restrict__ bias, float* __restrict__ out,
    int M, int N, int D, int relu)
{
    __shared__ uint32_t As[128 * LDS_];
    __shared__ uint32_t Bs[128 * LDS_];

    int tid = threadIdx.x;
    int lane = tid & 31, wid = tid >> 5;
    int wm = wid & 1;
    int wn = wid >> 1;
    int g = lane >> 2, t = lane & 3;

    int rowBase = blockIdx.x * 128, colBase = blockIdx.y * 128;

    float acc[4][4][4];
    #pragma unroll
    for (int i = 0; i < 4; i++)
        #pragma unroll
        for (int j = 0; j < 4; j++)
            #pragma unroll
            for (int r = 0; r < 4; r++) acc[i][j][r] = 0.f;

    int ldr = tid >> 3;
    int ldc = (tid & 7) * 4;

    for (int kt = 0; kt < 2 * D; kt += 32) {
        const float* A = (kt < D) ? A0 : A1;
        const float* W = (kt < D) ? Wl : Wr;
        int kk = (kt < D) ? kt : (kt - D);

        #pragma unroll
        for (int s = 0; s < 4; s++) {
            int r = ldr + s * 32;
            int grow = rowBase + r;
            float4 v = make_float4(0.f, 0.f, 0.f, 0.f);
            if (grow < M) v = *(const float4*)(A + (size_t)grow * D + kk + ldc);
            uint4 ua;
            ua.x = f2tf32(v.x); ua.y = f2tf32(v.y); ua.z = f2tf32(v.z); ua.w = f2tf32(v.w);
            *(uint4*)&As[r * LDS_ + ldc] = ua;
            float4 w = *(const float4*)(W + (size_t)(colBase + r) * D + kk + ldc);
            uint4 ub;
            ub.x = f2tf32(w.x); ub.y = f2tf32(w.y); ub.z = f2tf32(w.z); ub.w = f2tf32(w.w);
            *(uint4*)&Bs[r * LDS_ + ldc] = ub;
        }
        __syncthreads();

        #pragma unroll
        for (int ks = 0; ks < 32; ks += 8) {
            uint32_t af[4][4];
            #pragma unroll
            for (int mi = 0; mi < 4; mi++) {
                int m = wm * 64 + mi * 16;
                af[mi][0] = As[(m + g)     * LDS_ + ks + t];
                af[mi][1] = As[(m + g + 8) * LDS_ + ks + t];
                af[mi][2] = As[(m + g)     * LDS_ + ks + t + 4];
                af[mi][3] = As[(m + g + 8) * LDS_ + ks + t + 4];
            }
            uint32_t bf[4][2];
            #pragma unroll
            for (int ni = 0; ni < 4; ni++) {
                int n = wn * 32 + ni * 8;
                bf[ni][0] = Bs[(n + g) * LDS_ + ks + t];
                bf[ni][1] = Bs[(n + g) * LDS_ + ks + t + 4];
            }
            #pragma unroll
            for (int mi = 0; mi < 4; mi++)
                #pragma unroll
                for (int ni = 0; ni < 4; ni++) {
                    asm volatile(
                        "mma.sync.aligned.m16n8k8.row.col.f32.tf32.tf32.f32 "
                        "{%0,%1,%2,%3}, {%4,%5,%6,%7}, {%8,%9}, {%0,%1,%2,%3};"
                        : "+f"(acc[mi][ni][0]), "+f"(acc[mi][ni][1]),
                          "+f"(acc[mi][ni][2]), "+f"(acc[mi][ni][3])
                        : "r"(af[mi][0]), "r"(af[mi][1]), "r"(af[mi][2]), "r"(af[mi][3]),
                          "r"(bf[ni][0]), "r"(bf[ni][1]));
                }
        }
        __syncthreads();
    }

    #pragma unroll
    for (int mi = 0; mi < 4; mi++) {
        #pragma unroll
        for (int ni = 0; ni < 4; ni++) {
            int col = colBase + wn * 32 + ni * 8 + t * 2;
            float b0v = bias[col], b1v = bias[col + 1];
            int row0 = rowBase + wm * 64 + mi * 16 + g;
            if (row0 < M) {
                float2 o;
                o.x = acc[mi][ni][0] + b0v;
                o.y = acc[mi][ni][1] + b1v;
                if (relu) { o.x = fmaxf(o.x, 0.f); o.y = fmaxf(o.y, 0.f); }
                *(float2*)(out + (size_t)row0 * N + col) = o;
            }
            int row1 = row0 + 8;
            if (row1 < M) {
                float2 o;
                o.x = acc[mi][ni][2] + b0v;
                o.y = acc[mi][ni][3] + b1v;
                if (relu) { o.x = fmaxf(o.x, 0.f); o.y = fmaxf(o.y, 0.f); }
                *(float2*)(out + (size_t)row1 * N + col) = o;
            }
        }
    }
}

extern "C" void kernel_launch(void* const* d_in, const int* in_sizes, int n_in,
                              void* d_out, int out_size)
{
    const float* x    = (const float*)d_in[0];
    const int*   src0 = (const int*)d_in[1];
    const int*   dst0 = (const int*)d_in[2];
    const int*   src1 = (const int*)d_in[3];
    const int*   dst1 = (const int*)d_in[4];
    const int*   src2 = (const int*)d_in[5];
    const int*   dst2 = (const int*)d_in[6];
    const float* wl0  = (const float*)d_in[7];
    const float* wr0  = (const float*)d_in[8];
    const float* b0   = (const float*)d_in[9];
    const float* wl1  = (const float*)d_in[10];
    const float* wr1  = (const float*)d_in[11];
    const float* b1   = (const float*)d_in[12];
    const float* wl2  = (const float*)d_in[13];
    const float* wr2  = (const float*)d_in[14];
    const float* b2   = (const float*)d_in[15];
    float* out = (float*)d_out;

    cudaFuncSetAttribute(sage_gemm_wide,
                         cudaFuncAttributeMaxDynamicSharedMemorySize, WIDE_SMEM);

    float *h1, *h2, *mean;
    cudaGetSymbolAddress((void**)&h1, g_h1);
    cudaGetSymbolAddress((void**)&h2, g_h2);
    cudaGetSymbolAddress((void**)&mean, g_mean);
    int *off0, *off1, *off2, *es0, *es1, *es2;
    cudaGetSymbolAddress((void**)&off0, g_off0);
    cudaGetSymbolAddress((void**)&off1, g_off1);
    cudaGetSymbolAddress((void**)&off2, g_off2);
    cudaGetSymbolAddress((void**)&es0, g_esrc0);
    cudaGetSymbolAddress((void**)&es1, g_esrc1);
    cudaGetSymbolAddress((void**)&es2, g_esrc2);

    // Batched CSR build for all 3 layers
    const int NTOT = N1c + N2c + N3c;
    const int ETOT = E0c + E1c + E2c;
    zero3_kernel<<<(NTOT + 255) / 256, 256>>>();
    hist3_kernel<<<(ETOT + 255) / 256, 256>>>(dst0, dst1, dst2);
    scan3_kernel<<<3, 1024>>>();
    bucket3_kernel<<<(ETOT + 255) / 256, 256>>>(src0, dst0, src1, dst1, src2, dst2);

    // Layer 0: x (N0 x 128) -> h1 (N1 x 256), relu
    aggregate_kernel<128><<<(N1c * 32 + 255) / 256, 256>>>(x, mean, off0, es0, N1c);
    sage_gemm_wide<<<(N1c + 127) / 128, 512, WIDE_SMEM>>>(mean, x, wl0, wr0, b0, h1,
                                                          N1c, DINc, 1);
    // Layer 1: h1 (N1 x 256) -> h2 (N2 x 256), relu
    aggregate_kernel<256><<<(N2c * 32 + 255) / 256, 256>>>(h1, mean, off1, es1, N2c);
    sage_gemm_wide<<<(N2c + 127) / 128, 512, WIDE_SMEM>>>(mean, h1, wl1, wr1, b1, h2,
                                                          N2c, DHc, 1);
    // Layer 2: h2 (N2 x 256) -> out (N3 x 128), no relu
    aggregate_kernel<256><<<(N3c * 32 + 255) / 256, 256>>>(h2, mean, off2, es2, N3c);
    dim3 g2((N3c + 127) / 128, 1);
    sage_gemm_tf32<<<g2, 256>>>(mean, h2, wl2, wr2, b2, out, N3c, DOUTc, DHc, 0);
}

// round 11
// speedup vs baseline: 1.1188x; 1.0243x over previous
#include <cuda_runtime.h>
#include <cstdint>

// Problem constants (match reference_code)
#define N0c 200000
#define N1c 50000
#define N2c 12500
#define N3c 3200
#define E0c 500000
#define E1c 125000
#define E2c 32000
#define DINc 128
#define DHc 256
#define DOUTc 128

// ---------------- scratch (static device globals; no allocations) ----------------
__device__ float g_mean[(size_t)N1c * DHc];
__device__ float g_h1[(size_t)N1c * DHc];
__device__ float g_h2[(size_t)N2c * DHc];
__device__ int g_deg0[N1c]; __device__ int g_off0[N1c + 1]; __device__ int g_cur0[N1c]; __device__ int g_esrc0[E0c];
__device__ int g_deg1[N2c]; __device__ int g_off1[N2c + 1]; __device__ int g_cur1[N2c]; __device__ int g_esrc1[E1c];
__device__ int g_deg2[N3c]; __device__ int g_off2[N3c + 1]; __device__ int g_cur2[N3c]; __device__ int g_esrc2[E2c];

// ---------------- generic CSR kernels ----------------
__global__ void zero_k(int* deg, int n) {
    int i = blockIdx.x * blockDim.x + threadIdx.x;
    if (i < n) deg[i] = 0;
}

__global__ void hist_k(const int* __restrict__ dst, int* deg, int E) {
    int e = blockIdx.x * blockDim.x + threadIdx.x;
    if (e < E) atomicAdd(&deg[dst[e]], 1);
}

// One-pass chunked scan, single 1024-thread block.
__global__ void scan_k(const int* __restrict__ deg, int* off, int* cur, int n, int E) {
    const int T = 1024;
    __shared__ int wsum[32];
    int tid = threadIdx.x, lane = tid & 31, wid = tid >> 5;
    int chunk = (n + T - 1) / T;
    int beg = min(tid * chunk, n), end = min(beg + chunk, n);

    int sum = 0;
    for (int i = beg; i < end; i++) sum += deg[i];

    int s = sum;
    #pragma unroll
    for (int o = 1; o < 32; o <<= 1) {
        int t = __shfl_up_sync(0xffffffffu, s, o);
        if (lane >= o) s += t;
    }
    if (lane == 31) wsum[wid] = s;
    __syncthreads();
    if (wid == 0) {
        int ws = wsum[lane];
        #pragma unroll
        for (int o = 1; o < 32; o <<= 1) {
            int t = __shfl_up_sync(0xffffffffu, ws, o);
            if (lane >= o) ws += t;
        }
        wsum[lane] = ws;
    }
    __syncthreads();
    int excl = s - sum + ((wid > 0) ? wsum[wid - 1] : 0);

    int run = excl;
    for (int i = beg; i < end; i++) {
        int d = deg[i];
        off[i] = run;
        cur[i] = run;
        run += d;
    }
    if (tid == 0) off[n] = E;
}

__global__ void bucket_k(const int* __restrict__ src, const int* __restrict__ dst,
                         int* cur, int* esrc, int E) {
    int e = blockIdx.x * blockDim.x + threadIdx.x;
    if (e < E) {
        int p = atomicAdd(&cur[dst[e]], 1);
        esrc[p] = src[e];
    }
}

// ---------------- aggregation: warp per target node, node range [nb, ne) ----------------
template <int D>
__global__ void aggregate_kernel(const float* __restrict__ X, float* __restrict__ mean,
                                 const int* __restrict__ off, const int* __restrict__ esrc,
                                 int nb, int ne) {
    int w = nb + ((blockIdx.x * blockDim.x + threadIdx.x) >> 5);
    int lane = threadIdx.x & 31;
    if (w >= ne) return;
    int beg = off[w], end = off[w + 1];
    float acc[D / 32];
    #pragma unroll
    for (int i = 0; i < D / 32; i++) acc[i] = 0.f;
    int e = beg;
    for (; e + 1 < end; e += 2) {
        int s0 = esrc[e], s1 = esrc[e + 1];
        const float4* r0 = (const float4*)(X + (size_t)s0 * D);
        const float4* r1 = (const float4*)(X + (size_t)s1 * D);
        #pragma unroll
        for (int i = 0; i < D / 128; i++) {
            float4 v0 = r0[lane + 32 * i];
            float4 v1 = r1[lane + 32 * i];
            acc[4 * i + 0] += v0.x + v1.x;
            acc[4 * i + 1] += v0.y + v1.y;
            acc[4 * i + 2] += v0.z + v1.z;
            acc[4 * i + 3] += v0.w + v1.w;
        }
    }
    if (e < end) {
        const float4* row = (const float4*)(X + (size_t)esrc[e] * D);
        #pragma unroll
        for (int i = 0; i < D / 128; i++) {
            float4 v = row[lane + 32 * i];
            acc[4 * i + 0] += v.x;
            acc[4 * i + 1] += v.y;
            acc[4 * i + 2] += v.z;
            acc[4 * i + 3] += v.w;
        }
    }
    float inv = 1.f / (float)max(end - beg, 1);
    float4* mrow = (float4*)(mean + (size_t)w * D);
    #pragma unroll
    for (int i = 0; i < D / 128; i++) {
        float4 o;
        o.x = acc[4 * i + 0] * inv;
        o.y = acc[4 * i + 1] * inv;
        o.z = acc[4 * i + 2] * inv;
        o.w = acc[4 * i + 3] * inv;
        mrow[lane + 32 * i] = o;
    }
}

// ---------------- R2 tf32 GEMM with row offset (chunked) ----------------
__device__ __forceinline__ uint32_t f2tf32(float f) {
    uint32_t u;
    asm("cvt.rna.tf32.f32 %0, %1;" : "=r"(u) : "f"(f));
    return u;
}

#define LDS_ 36

__global__ void __launch_bounds__(256) sage_gemm_tf32(
    const float* __restrict__ A0, const float* __restrict__ A1,
    const float* __restrict__ Wl, const float* __restrict__ Wr,
    const float* __restrict__ bias, float* __restrict__ out,
    int rowOffset, int Mlim, int N, int D, int relu)
{
    __shared__ uint32_t As[128 * LDS_];
    __shared__ uint32_t Bs[128 * LDS_];

    int tid = threadIdx.x;
    int lane = tid & 31, wid = tid >> 5;
    int wm = wid & 1;
    int wn = wid >> 1;
    int g = lane >> 2, t = lane & 3;

    int rowBase = rowOffset + blockIdx.x * 128, colBase = blockIdx.y * 128;

    float acc[4][4][4];
    #pragma unroll
    for (int i = 0; i < 4; i++)
        #pragma unroll
        for (int j = 0; j < 4; j++)
            #pragma unroll
            for (int r = 0; r < 4; r++) acc[i][j][r] = 0.f;

    int ldr = tid >> 3;
    int ldc = (tid & 7) * 4;

    for (int kt = 0; kt < 2 * D; kt += 32) {
        const float* A = (kt < D) ? A0 : A1;
        const float* W = (kt < D) ? Wl : Wr;
        int kk = (kt < D) ? kt : (kt - D);

        #pragma unroll
        for (int s = 0; s < 4; s++) {
            int r = ldr + s * 32;
            int grow = rowBase + r;
            float4 v = make_float4(0.f, 0.f, 0.f, 0.f);
            if (grow < Mlim) v = *(const float4*)(A + (size_t)grow * D + kk + ldc);
            uint4 ua;
            ua.x = f2tf32(v.x); ua.y = f2tf32(v.y); ua.z = f2tf32(v.z); ua.w = f2tf32(v.w);
            *(uint4*)&As[r * LDS_ + ldc] = ua;
            float4 w = *(const float4*)(W + (size_t)(colBase + r) * D + kk + ldc);
            uint4 ub;
            ub.x = f2tf32(w.x); ub.y = f2tf32(w.y); ub.z = f2tf32(w.z); ub.w = f2tf32(w.w);
            *(uint4*)&Bs[r * LDS_ + ldc] = ub;
        }
        __syncthreads();

        #pragma unroll
        for (int ks = 0; ks < 32; ks += 8) {
            uint32_t af[4][4];
            #pragma unroll
            for (int mi = 0; mi < 4; mi++) {
                int m = wm * 64 + mi * 16;
                af[mi][0] = As[(m + g)     * LDS_ + ks + t];
                af[mi][1] = As[(m + g + 8) * LDS_ + ks + t];
                af[mi][2] = As[(m + g)     * LDS_ + ks + t + 4];
                af[mi][3] = As[(m + g + 8) * LDS_ + ks + t + 4];
            }
            uint32_t bf[4][2];
            #pragma unroll
            for (int ni = 0; ni < 4; ni++) {
                int n = wn * 32 + ni * 8;
                bf[ni][0] = Bs[(n + g) * LDS_ + ks + t];
                bf[ni][1] = Bs[(n + g) * LDS_ + ks + t + 4];
            }
            #pragma unroll
            for (int mi = 0; mi < 4; mi++)
                #pragma unroll
                for (int ni = 0; ni < 4; ni++) {
                    asm volatile(
                        "mma.sync.aligned.m16n8k8.row.col.f32.tf32.tf32.f32 "
                        "{%0,%1,%2,%3}, {%4,%5,%6,%7}, {%8,%9}, {%0,%1,%2,%3};"
                        : "+f"(acc[mi][ni][0]), "+f"(acc[mi][ni][1]),
                          "+f"(acc[mi][ni][2]), "+f"(acc[mi][ni][3])
                        : "r"(af[mi][0]), "r"(af[mi][1]), "r"(af[mi][2]), "r"(af[mi][3]),
                          "r"(bf[ni][0]), "r"(bf[ni][1]));
                }
        }
        __syncthreads();
    }

    #pragma unroll
    for (int mi = 0; mi < 4; mi++) {
        #pragma unroll
        for (int ni = 0; ni < 4; ni++) {
            int col = colBase + wn * 32 + ni * 8 + t * 2;
            float b0v = bias[col], b1v = bias[col + 1];
            int row0 = rowBase + wm * 64 + mi * 16 + g;
            if (row0 < Mlim) {
                float2 o;
                o.x = acc[mi][ni][0] + b0v;
                o.y = acc[mi][ni][1] + b1v;
                if (relu) { o.x = fmaxf(o.x, 0.f); o.y = fmaxf(o.y, 0.f); }
                *(float2*)(out + (size_t)row0 * N + col) = o;
            }
            int row1 = row0 + 8;
            if (row1 < Mlim) {
                float2 o;
                o.x = acc[mi][ni][2] + b0v;
                o.y = acc[mi][ni][3] + b1v;
                if (relu) { o.x = fmaxf(o.x, 0.f); o.y = fmaxf(o.y, 0.f); }
                *(float2*)(out + (size_t)row1 * N + col) = o;
            }
        }
    }
}

// ---------------- host-side: chunk helpers ----------------
template <int D>
static void launch_chunk(cudaStream_t s, const float* X, float* mean,
                         const int* off, const int* esrc,
                         int nb, int ne,
                         const float* Wl, const float* Wr, const float* b,
                         float* outbuf, int Nout, int relu)
{
    int nodes = ne - nb;
    int aggBlocks = (nodes * 32 + 255) / 256;
    aggregate_kernel<D><<<aggBlocks, 256, 0, s>>>(X, mean, off, esrc, nb, ne);
    dim3 grid((nodes + 127) / 128, Nout / 128);
    sage_gemm_tf32<<<grid, 256, 0, s>>>(mean, X, Wl, Wr, b, outbuf, nb, ne, Nout, D, relu);
}

extern "C" void kernel_launch(void* const* d_in, const int* in_sizes, int n_in,
                              void* d_out, int out_size)
{
    const float* x    = (const float*)d_in[0];
    const int*   src0 = (const int*)d_in[1];
    const int*   dst0 = (const int*)d_in[2];
    const int*   src1 = (const int*)d_in[3];
    const int*   dst1 = (const int*)d_in[4];
    const int*   src2 = (const int*)d_in[5];
    const int*   dst2 = (const int*)d_in[6];
    const float* wl0  = (const float*)d_in[7];
    const float* wr0  = (const float*)d_in[8];
    const float* b0   = (const float*)d_in[9];
    const float* wl1  = (const float*)d_in[10];
    const float* wr1  = (const float*)d_in[11];
    const float* b1   = (const float*)d_in[12];
    const float* wl2  = (const float*)d_in[13];
    const float* wr2  = (const float*)d_in[14];
    const float* b2   = (const float*)d_in[15];
    float* out = (float*)d_out;

    // one-time stream/event setup (host objects only; created during the eager
    // correctness call, reused inside graph capture)
    static cudaStream_t sB = nullptr, sC = nullptr;
    static cudaEvent_t evRoot, evCsr0, evC, evM0, evB0, evB1;
    if (!sB) {
        cudaStreamCreateWithFlags(&sB, cudaStreamNonBlocking);
        cudaStreamCreateWithFlags(&sC, cudaStreamNonBlocking);
        cudaEventCreateWithFlags(&evRoot, cudaEventDisableTiming);
        cudaEventCreateWithFlags(&evCsr0, cudaEventDisableTiming);
        cudaEventCreateWithFlags(&evC,    cudaEventDisableTiming);
        cudaEventCreateWithFlags(&evM0,   cudaEventDisableTiming);
        cudaEventCreateWithFlags(&evB0,   cudaEventDisableTiming);
        cudaEventCreateWithFlags(&evB1,   cudaEventDisableTiming);
    }

    float *h1, *h2, *mean;
    cudaGetSymbolAddress((void**)&h1, g_h1);
    cudaGetSymbolAddress((void**)&h2, g_h2);
    cudaGetSymbolAddress((void**)&mean, g_mean);
    int *deg0, *off0, *cur0, *es0, *deg1, *off1, *cur1, *es1, *deg2, *off2, *cur2, *es2;
    cudaGetSymbolAddress((void**)&deg0, g_deg0);
    cudaGetSymbolAddress((void**)&off0, g_off0);
    cudaGetSymbolAddress((void**)&cur0, g_cur0);
    cudaGetSymbolAddress((void**)&es0, g_esrc0);
    cudaGetSymbolAddress((void**)&deg1, g_deg1);
    cudaGetSymbolAddress((void**)&off1, g_off1);
    cudaGetSymbolAddress((void**)&cur1, g_cur1);
    cudaGetSymbolAddress((void**)&es1, g_esrc1);
    cudaGetSymbolAddress((void**)&deg2, g_deg2);
    cudaGetSymbolAddress((void**)&off2, g_off2);
    cudaGetSymbolAddress((void**)&cur2, g_cur2);
    cudaGetSymbolAddress((void**)&es2, g_esrc2);

    // ---- fork sC: CSR for layers 1 & 2 in the background ----
    cudaEventRecord(evRoot, 0);
    cudaStreamWaitEvent(sC, evRoot, 0);
    zero_k<<<(N2c + 255) / 256, 256, 0, sC>>>(deg1, N2c);
    hist_k<<<(E1c + 255) / 256, 256, 0, sC>>>(dst1, deg1, E1c);
    scan_k<<<1, 1024, 0, sC>>>(deg1, off1, cur1, N2c, E1c);
    bucket_k<<<(E1c + 255) / 256, 256, 0, sC>>>(src1, dst1, cur1, es1, E1c);
    zero_k<<<(N3c + 255) / 256, 256, 0, sC>>>(deg2, N3c);
    hist_k<<<(E2c + 255) / 256, 256, 0, sC>>>(dst2, deg2, E2c);
    scan_k<<<1, 1024, 0, sC>>>(deg2, off2, cur2, N3c, E2c);
    bucket_k<<<(E2c + 255) / 256, 256, 0, sC>>>(src2, dst2, cur2, es2, E2c);
    cudaEventRecord(evC, sC);

    // ---- main stream: CSR layer 0 ----
    zero_k<<<(N1c + 255) / 256, 256>>>(deg0, N1c);
    hist_k<<<(E0c + 255) / 256, 256>>>(dst0, deg0, E0c);
    scan_k<<<1, 1024>>>(deg0, off0, cur0, N1c, E0c);
    bucket_k<<<(E0c + 255) / 256, 256>>>(src0, dst0, cur0, es0, E0c);
    cudaEventRecord(evCsr0, 0);
    cudaStreamWaitEvent(sB, evCsr0, 0);

    // ---- Layer 0: 4 chunks, ping-pong main/sB ----
    // chunk bounds (128-aligned starts)
    const int c0[5] = {0, 12544, 25088, 37632, N1c};
    launch_chunk<128>(0,  x, mean, off0, es0, c0[0], c0[1], wl0, wr0, b0, h1, DHc, 1);
    launch_chunk<128>(sB, x, mean, off0, es0, c0[1], c0[2], wl0, wr0, b0, h1, DHc, 1);
    launch_chunk<128>(0,  x, mean, off0, es0, c0[2], c0[3], wl0, wr0, b0, h1, DHc, 1);
    launch_chunk<128>(sB, x, mean, off0, es0, c0[3], c0[4], wl0, wr0, b0, h1, DHc, 1);
    cudaEventRecord(evM0, 0);
    cudaEventRecord(evB0, sB);
    cudaStreamWaitEvent(0, evB0, 0);     // main sees all h1
    cudaStreamWaitEvent(0, evC, 0);      // main sees CSR1/CSR2
    cudaStreamWaitEvent(sB, evM0, 0);    // sB sees main's h1
    cudaStreamWaitEvent(sB, evC, 0);     // sB sees CSR1

    // ---- Layer 1: 2 chunks ----
    const int c1[3] = {0, 6272, N2c};
    launch_chunk<256>(0,  h1, mean, off1, es1, c1[0], c1[1], wl1, wr1, b1, h2, DHc, 1);
    launch_chunk<256>(sB, h1, mean, off1, es1, c1[1], c1[2], wl1, wr1, b1, h2, DHc, 1);
    cudaEventRecord(evB1, sB);
    cudaStreamWaitEvent(0, evB1, 0);     // join sB before layer 2

    // ---- Layer 2: single chunk on main ----
    launch_chunk<256>(0, h2, mean, off2, es2, 0, N3c, wl2, wr2, b2, out, DOUTc, 0);
}